// round 15
// baseline (speedup 1.0000x reference)
#include <cuda_runtime.h>
#include <cuda_fp16.h>
#include <cstdint>

// ---------------------------------------------------------------------------
// effConvKAN3D as f16 HMMA GEMM. K split across CTAs (atomicAdd combine):
//   kh=0: spline chunks 0..60   (features 0..121,  channels 0..4)
//   kh=1: spline chunks 61..107 (features 122..215, channels 4..7) + 14 silu
// Per-CTA smem: half-B (31KB) + basis tile (49/39KB) + silu tile (kh=1).
// All main-loop A fragments are conflict-free LDS from the staged tiles.
// ---------------------------------------------------------------------------

#define NF      216
#define OSTRIDE 32768
#define NCH     122
#define HCH     61

#define BH_BYTES (HCH * 512)            // 31232
#define BH_U4    (BH_BYTES / 16)
#define BT_OFF   BH_BYTES               // basis tile (5 or 4 channels)
#define BT0_U4   (5 * 612)              // 3060 uint4 (kh=0)
#define BT1_U4   (4 * 612)              // 2448 uint4 (kh=1)
#define ST_OFF   (BT_OFF + BT1_U4 * 16) // 70400 (kh=1 silu tile)
#define ST_HALVES 5040                  // 4896 + 144 zero pad
#define ZOFF     (4896 * 2)
#define TBL_OFF  (ST_OFF + ST_HALVES * 2)   // 80480
#define SMEM_TOTAL (TBL_OFF + 896)          // 81376 -> 2 CTAs/SM

#define NB_ITEMS   (NCH * 128)            // 15616
#define NBAS_ITEMS (8 * 34 * 34 * 34)     // 314432
#define PREP_TOTAL (NB_ITEMS + 2 * NBAS_ITEMS)

__device__ __align__(16) uint4    g_basis[NBAS_ITEMS];
__device__ __align__(16) __half   g_silv[NBAS_ITEMS];
__device__ __align__(16) uint32_t g_Bf[NB_ITEMS];

__device__ __forceinline__ uint4 basis_row(float v) {
    float tt = fmaf(v, 2.5f, 5.5f);
    float jf = floorf(tt);
    float u = tt - jf;
    int j = (int)jf;
    float u2 = u * u, u3 = u2 * u, om = 1.0f - u;
    float b0 = om * om * om * (1.0f / 6.0f);
    float b1 = fmaf(3.0f, u3, fmaf(-6.0f, u2, 4.0f)) * (1.0f / 6.0f);
    float b2 = fmaf(-3.0f, u3, fmaf(3.0f, u2, fmaf(3.0f, u, 1.0f))) * (1.0f / 6.0f);
    float b3 = u3 * (1.0f / 6.0f);
    __half2 hlo = __floats2half2_rn(b0, b1);
    __half2 hhi = __floats2half2_rn(b2, b3);
    uint32_t lo = *(uint32_t*)&hlo, hi = *(uint32_t*)&hhi;
    if ((unsigned)j > 10u) { lo = 0u; hi = 0u; j = 3; }
    uint64_t B64 = (uint64_t)lo | ((uint64_t)hi << 32);
    int t16 = j - 3;
    uint32_t wv[4];
    #pragma unroll
    for (int i = 0; i < 4; i++) {
        int d = 2 * i - t16;
        int shc = ((unsigned)d <= 3u) ? d : 0;
        uint32_t a = (uint32_t)(B64 >> (shc * 16));
        wv[i] = ((unsigned)d <= 3u) ? a : ((d == -1) ? (lo << 16) : 0u);
    }
    return make_uint4(wv[0], wv[1], wv[2], wv[3]);
}

__device__ __forceinline__ float bval(int o, int k,
                                      const float* __restrict__ bw,
                                      const float* __restrict__ sw,
                                      const float* __restrict__ sc) {
    int kc = k >> 4, col = k & 15;
    if (kc < 108) {
        int f = 2 * kc + (col >> 3), c = col & 7;
        return sw[(o * NF + f) * 8 + c] * sc[o * NF + f];
    }
    int f = 16 * (kc - 108) + col;
    return (f < NF) ? bw[o * NF + f] : 0.0f;
}

__device__ __forceinline__ float padval(const float* __restrict__ x, int t) {
    int c  = t / 39304;
    int r1 = t - c * 39304;
    int iz = r1 / 1156;
    int r2 = r1 - iz * 1156;
    int iy = r2 / 34;
    int ix = r2 - iy * 34;
    int az = iz - 1, ay = iy - 1, ax = ix - 1;
    if (((unsigned)az < 32u) & ((unsigned)ay < 32u) & ((unsigned)ax < 32u))
        return x[((c * 32 + az) * 32 + ay) * 32 + ax];
    return 0.0f;
}

__global__ void prep_all(const float* __restrict__ x,
                         const float* __restrict__ bw,
                         const float* __restrict__ sw,
                         const float* __restrict__ sc) {
    int t = blockIdx.x * 256 + threadIdx.x;
    if (t < NB_ITEMS) {
        int wd = t & 3, lane = (t >> 2) & 31, kc = t >> 7;
        int g8 = lane >> 2, t4 = lane & 3;
        int o = g8 + ((wd >> 1) << 3);
        int kb = kc * 16 + ((wd & 1) << 3) + 2 * t4;
        __half2 h = __floats2half2_rn(bval(o, kb, bw, sw, sc),
                                      bval(o, kb + 1, bw, sw, sc));
        g_Bf[t] = *(uint32_t*)&h;
        return;
    }
    t -= NB_ITEMS;
    if (t < NBAS_ITEMS) { g_basis[t] = basis_row(padval(x, t)); return; }
    t -= NBAS_ITEMS;
    if (t < NBAS_ITEMS) {
        float v = padval(x, t);
        g_silv[t] = __float2half_rn(__fdividef(v, 1.0f + __expf(-v)));
    }
}

// compile-time tile byte offset for feature f (channel base cb)
__device__ __forceinline__ uint32_t offBT(int f, int cb) {
    int c = f / 27, r = f - 27 * c;
    int dz = r / 9,  r2 = r - 9 * dz;
    int dy = r2 / 3, dx = r2 - 3 * dy;
    return (uint32_t)(((((c - cb) * 3 + dz) * 6 + dy) * 34 + dx) * 16);
}

#define MMA2(A0, A1, A2, A3, CB) do {                                         \
    asm volatile("mma.sync.aligned.m16n8k16.row.col.f32.f16.f16.f32 "         \
        "{%0,%1,%2,%3}, {%4,%5,%6,%7}, {%8,%9}, {%0,%1,%2,%3};"               \
        : "+f"(d[0]), "+f"(d[1]), "+f"(d[2]), "+f"(d[3])                      \
        : "r"(A0), "r"(A1), "r"(A2), "r"(A3), "r"((CB).x), "r"((CB).y));      \
    asm volatile("mma.sync.aligned.m16n8k16.row.col.f32.f16.f16.f32 "         \
        "{%0,%1,%2,%3}, {%4,%5,%6,%7}, {%8,%9}, {%0,%1,%2,%3};"               \
        : "+f"(d[4]), "+f"(d[5]), "+f"(d[6]), "+f"(d[7])                      \
        : "r"(A0), "r"(A1), "r"(A2), "r"(A3), "r"((CB).z), "r"((CB).w));      \
} while (0)

#define SPLINE_CHUNK(KC, LC, CBASE) do {                                      \
    const uint32_t oA_ = offBT(2 * (KC), CBASE);                              \
    const uint32_t oB_ = offBT(2 * (KC) + 1, CBASE);                          \
    uint32_t a0_ = *(const uint32_t*)(btA + oA_);                             \
    uint32_t a1_ = *(const uint32_t*)(btA + oA_ + 128);                       \
    uint32_t a2_ = *(const uint32_t*)(btA + oB_);                             \
    uint32_t a3_ = *(const uint32_t*)(btA + oB_ + 128);                       \
    uint4 cb_ = *(const uint4*)(bp + (LC) * 512);                             \
    MMA2(a0_, a1_, a2_, a3_, cb_);                                            \
} while (0)

__global__ __launch_bounds__(256, 2)
void kan_kernel(float* __restrict__ out) {
    extern __shared__ char smem[];
    const int tid = threadIdx.x;
    const int bid = blockIdx.x;
    const int kh = bid & 1;
    const int pb = bid >> 1;
    const int z0 = pb >> 3, y0 = (pb & 7) * 4;

    // half-B fragments
    {
        const uint4* srcB = (const uint4*)(g_Bf + (kh ? HCH * 128 : 0));
        for (int i = tid; i < BH_U4; i += 256)
            ((uint4*)smem)[i] = srcB[i];
    }
    // basis tile: [cc][dz 3][iy 6][ix 34] of 16B rows
    {
        const int cb = kh ? 4 : 0;
        const int n = kh ? BT1_U4 : BT0_U4;
        uint4* bt = (uint4*)(smem + BT_OFF);
        for (int i = tid; i < n; i += 256) {
            int cc = i / 612;
            int r  = i - cc * 612;
            int dz = r / 204;
            int r2 = r - dz * 204;
            int iy = r2 / 34;
            int ix = r2 - iy * 34;
            bt[i] = g_basis[(cc + cb) * 39304 + (z0 + dz) * 1156 +
                            (y0 + iy) * 34 + ix];
        }
    }
    if (kh) {
        // silu tile [c 8][dz 3][iy 6][ix 34] halves + zero pad
        unsigned short* st = (unsigned short*)(smem + ST_OFF);
        for (int i = tid; i < ST_HALVES; i += 256) {
            unsigned short v = 0;
            if (i < 4896) {
                int c  = i / 612;
                int r  = i - c * 612;
                int dz = r / 204;
                int r2 = r - dz * 204;
                int iy = r2 / 34;
                int ix = r2 - iy * 34;
                v = ((const unsigned short*)g_silv)
                        [c * 39304 + (z0 + dz) * 1156 + (y0 + iy) * 34 + ix];
            }
            st[i] = v;
        }
        if (tid < 224) {
            uint32_t off = ZOFF;
            if (tid < NF) {
                int c = tid / 27, r = tid - 27 * c;
                int dz = r / 9,  r2 = r - 9 * dz;
                int dy = r2 / 3, dx = r2 - 3 * dy;
                off = (uint32_t)((((c * 3 + dz) * 6 + dy) * 34 + dx) * 2);
            }
            ((uint32_t*)(smem + TBL_OFF))[tid] = off;
        }
    }
    __syncthreads();

    const int wid = tid >> 5, lane = tid & 31;
    const int g8 = lane >> 2, t4 = lane & 3;
    const int yl = wid >> 1, xs = (wid & 1) * 16;
    const int pos0 = z0 * 1024 + (y0 + yl) * 32 + xs;

    const char* btA = smem + BT_OFF + (uint32_t)((yl * 34 + xs) * 16 + lane * 4);
    const char* bp  = smem + lane * 16;

    float d[8];
    #pragma unroll
    for (int i = 0; i < 8; i++) d[i] = 0.0f;

    if (kh == 0) {
        #pragma unroll
        for (int kc = 0; kc < 61; kc++) SPLINE_CHUNK(kc, kc, 0);
    } else {
        #pragma unroll
        for (int kc = 61; kc < 108; kc++) SPLINE_CHUNK(kc, kc - 61, 4);
        const char* stb = smem + ST_OFF + (uint32_t)((yl * 34 + xs + g8) * 2);
        const uint32_t* tbl = (const uint32_t*)(smem + TBL_OFF);
        #pragma unroll
        for (int g = 0; g < 14; g++) {
            uint32_t p0 = tbl[16 * g + 2 * t4];
            uint32_t p1 = tbl[16 * g + 2 * t4 + 1];
            uint32_t p2 = tbl[16 * g + 8 + 2 * t4];
            uint32_t p3 = tbl[16 * g + 9 + 2 * t4];
            uint32_t v00 = *(const unsigned short*)(stb + p0);
            uint32_t v01 = *(const unsigned short*)(stb + p1);
            uint32_t v10 = *(const unsigned short*)(stb + p0 + 16);
            uint32_t v11 = *(const unsigned short*)(stb + p1 + 16);
            uint32_t v20 = *(const unsigned short*)(stb + p2);
            uint32_t v21 = *(const unsigned short*)(stb + p3);
            uint32_t v30 = *(const unsigned short*)(stb + p2 + 16);
            uint32_t v31 = *(const unsigned short*)(stb + p3 + 16);
            uint32_t a0 = v00 | (v01 << 16);
            uint32_t a1 = v10 | (v11 << 16);
            uint32_t a2 = v20 | (v21 << 16);
            uint32_t a3 = v30 | (v31 << 16);
            uint4 cb = *(const uint4*)(bp + (47 + g) * 512);
            MMA2(a0, a1, a2, a3, cb);
        }
    }

    // combine K halves via atomics into zeroed output
    const int pr0 = pos0 + g8, pr1 = pr0 + 8;
    atomicAdd(&out[(2 * t4 + 0) * OSTRIDE + pr0], d[0]);
    atomicAdd(&out[(2 * t4 + 1) * OSTRIDE + pr0], d[1]);
    atomicAdd(&out[(2 * t4 + 0) * OSTRIDE + pr1], d[2]);
    atomicAdd(&out[(2 * t4 + 1) * OSTRIDE + pr1], d[3]);
    atomicAdd(&out[(2 * t4 + 8) * OSTRIDE + pr0], d[4]);
    atomicAdd(&out[(2 * t4 + 9) * OSTRIDE + pr0], d[5]);
    atomicAdd(&out[(2 * t4 + 8) * OSTRIDE + pr1], d[6]);
    atomicAdd(&out[(2 * t4 + 9) * OSTRIDE + pr1], d[7]);
}

extern "C" void kernel_launch(void* const* d_in, const int* in_sizes, int n_in,
                              void* d_out, int out_size) {
    const float* x  = (const float*)d_in[0];
    const float* bw = (const float*)d_in[1];
    const float* sw = (const float*)d_in[2];
    const float* sc = (const float*)d_in[3];

    cudaMemsetAsync(d_out, 0, (size_t)out_size * sizeof(float));
    prep_all<<<(PREP_TOTAL + 255) / 256, 256>>>(x, bw, sw, sc);

    cudaFuncSetAttribute(kan_kernel, cudaFuncAttributeMaxDynamicSharedMemorySize,
                         SMEM_TOTAL);
    kan_kernel<<<512, 256, SMEM_TOTAL>>>((float*)d_out);
}

// round 16
// speedup vs baseline: 1.3372x; 1.3372x over previous
#include <cuda_runtime.h>
#include <cuda_fp16.h>
#include <cstdint>

// ---------------------------------------------------------------------------
// effConvKAN3D as f16 HMMA GEMM, A and B fragments loaded directly from
// global (NO shared memory -> full 228KB L1 caches B (62.5KB, shared by all
// warps) and the basis rows (9x line reuse)). K split 4 ways across CTAs:
//   kq=0: spline chunks 0..30    kq=1: 31..60
//   kq=2: 61..91                 kq=3: 92..107 + 14 silu chunks
// Combine via atomicAdd into zeroed output.
// ---------------------------------------------------------------------------

#define NF      216
#define OSTRIDE 32768
#define NCH     122

#define NT_ITEMS   224
#define NB_ITEMS   (NCH * 128)            // 15616
#define NBAS_ITEMS (8 * 34 * 34 * 34)     // 314432
#define PREP_TOTAL (NT_ITEMS + NB_ITEMS + 2 * NBAS_ITEMS)

__device__ __align__(16) uint4    g_basis[NBAS_ITEMS];
__device__ __align__(16) __half   g_silv[NBAS_ITEMS];
__device__ __align__(16) uint32_t g_Bf[NB_ITEMS];
__device__ __align__(16) uint32_t g_offT[NT_ITEMS];

__device__ __forceinline__ uint4 basis_row(float v) {
    float tt = fmaf(v, 2.5f, 5.5f);
    float jf = floorf(tt);
    float u = tt - jf;
    int j = (int)jf;
    float u2 = u * u, u3 = u2 * u, om = 1.0f - u;
    float b0 = om * om * om * (1.0f / 6.0f);
    float b1 = fmaf(3.0f, u3, fmaf(-6.0f, u2, 4.0f)) * (1.0f / 6.0f);
    float b2 = fmaf(-3.0f, u3, fmaf(3.0f, u2, fmaf(3.0f, u, 1.0f))) * (1.0f / 6.0f);
    float b3 = u3 * (1.0f / 6.0f);
    __half2 hlo = __floats2half2_rn(b0, b1);
    __half2 hhi = __floats2half2_rn(b2, b3);
    uint32_t lo = *(uint32_t*)&hlo, hi = *(uint32_t*)&hhi;
    if ((unsigned)j > 10u) { lo = 0u; hi = 0u; j = 3; }
    uint64_t B64 = (uint64_t)lo | ((uint64_t)hi << 32);
    int t16 = j - 3;
    uint32_t wv[4];
    #pragma unroll
    for (int i = 0; i < 4; i++) {
        int d = 2 * i - t16;
        int shc = ((unsigned)d <= 3u) ? d : 0;
        uint32_t a = (uint32_t)(B64 >> (shc * 16));
        wv[i] = ((unsigned)d <= 3u) ? a : ((d == -1) ? (lo << 16) : 0u);
    }
    return make_uint4(wv[0], wv[1], wv[2], wv[3]);
}

__device__ __forceinline__ float bval(int o, int k,
                                      const float* __restrict__ bw,
                                      const float* __restrict__ sw,
                                      const float* __restrict__ sc) {
    int kc = k >> 4, col = k & 15;
    if (kc < 108) {
        int f = 2 * kc + (col >> 3), c = col & 7;
        return sw[(o * NF + f) * 8 + c] * sc[o * NF + f];
    }
    int f = 16 * (kc - 108) + col;
    return (f < NF) ? bw[o * NF + f] : 0.0f;
}

__device__ __forceinline__ float padval(const float* __restrict__ x, int t) {
    int c  = t / 39304;
    int r1 = t - c * 39304;
    int iz = r1 / 1156;
    int r2 = r1 - iz * 1156;
    int iy = r2 / 34;
    int ix = r2 - iy * 34;
    int az = iz - 1, ay = iy - 1, ax = ix - 1;
    if (((unsigned)az < 32u) & ((unsigned)ay < 32u) & ((unsigned)ax < 32u))
        return x[((c * 32 + az) * 32 + ay) * 32 + ax];
    return 0.0f;          // reference zero-pads x
}

__global__ void prep_all(const float* __restrict__ x,
                         const float* __restrict__ bw,
                         const float* __restrict__ sw,
                         const float* __restrict__ sc) {
    int t = blockIdx.x * 256 + threadIdx.x;
    if (t < NT_ITEMS) {                       // feature -> padded-volume offset
        uint32_t off = 0;
        if (t < NF) {
            int c = t / 27, r = t - c * 27;
            int dz = r / 9,  r2 = r - dz * 9;
            int dy = r2 / 3, dx = r2 - dy * 3;
            off = (uint32_t)(c * 39304 + dz * 1156 + dy * 34 + dx);
        }
        g_offT[t] = off;
        return;
    }
    t -= NT_ITEMS;
    if (t < NB_ITEMS) {                       // B fragments
        int wd = t & 3, lane = (t >> 2) & 31, kc = t >> 7;
        int g8 = lane >> 2, t4 = lane & 3;
        int o = g8 + ((wd >> 1) << 3);
        int kb = kc * 16 + ((wd & 1) << 3) + 2 * t4;
        __half2 h = __floats2half2_rn(bval(o, kb, bw, sw, sc),
                                      bval(o, kb + 1, bw, sw, sc));
        g_Bf[t] = *(uint32_t*)&h;
        return;
    }
    t -= NB_ITEMS;
    if (t < NBAS_ITEMS) { g_basis[t] = basis_row(padval(x, t)); return; }
    t -= NBAS_ITEMS;
    if (t < NBAS_ITEMS) {
        float v = padval(x, t);
        g_silv[t] = __float2half_rn(__fdividef(v, 1.0f + __expf(-v)));
    }
}

// compile-time basis-array byte offset for feature f
__device__ __forceinline__ uint32_t offB(int f) {
    int c = f / 27, r = f - c * 27;
    int dz = r / 9,  r2 = r - dz * 9;
    int dy = r2 / 3, dx = r2 - dy * 3;
    return (uint32_t)((c * 39304 + dz * 1156 + dy * 34 + dx) * 16);
}

#define MMA2(A0, A1, A2, A3, CB) do {                                         \
    asm volatile("mma.sync.aligned.m16n8k16.row.col.f32.f16.f16.f32 "         \
        "{%0,%1,%2,%3}, {%4,%5,%6,%7}, {%8,%9}, {%0,%1,%2,%3};"               \
        : "+f"(d[0]), "+f"(d[1]), "+f"(d[2]), "+f"(d[3])                      \
        : "r"(A0), "r"(A1), "r"(A2), "r"(A3), "r"((CB).x), "r"((CB).y));      \
    asm volatile("mma.sync.aligned.m16n8k16.row.col.f32.f16.f16.f32 "         \
        "{%0,%1,%2,%3}, {%4,%5,%6,%7}, {%8,%9}, {%0,%1,%2,%3};"               \
        : "+f"(d[4]), "+f"(d[5]), "+f"(d[6]), "+f"(d[7])                      \
        : "r"(A0), "r"(A1), "r"(A2), "r"(A3), "r"((CB).z), "r"((CB).w));      \
} while (0)

#define SPLINE_CHUNK(KC) do {                                                 \
    const uint32_t oA_ = offB(2 * (KC));                                      \
    const uint32_t oB_ = offB(2 * (KC) + 1);                                  \
    uint32_t a0_ = __ldg((const uint32_t*)(baseA + oA_));                     \
    uint32_t a1_ = __ldg((const uint32_t*)(baseA + oA_ + 128));               \
    uint32_t a2_ = __ldg((const uint32_t*)(baseA + oB_));                     \
    uint32_t a3_ = __ldg((const uint32_t*)(baseA + oB_ + 128));               \
    uint4 cb_ = __ldg((const uint4*)(bfp + (KC) * 512));                      \
    MMA2(a0_, a1_, a2_, a3_, cb_);                                            \
} while (0)

__global__ __launch_bounds__(256, 4)
void kan_kernel(float* __restrict__ out) {
    const int tid = threadIdx.x;
    const int bid = blockIdx.x;
    const int kq = bid & 3;          // K quarter
    const int pb = bid >> 2;         // position block (128 positions)

    const int wid = tid >> 5, lane = tid & 31;
    const int g8 = lane >> 2, t4 = lane & 3;
    const int z0 = pb >> 3, y0 = (pb & 7) * 4;
    const int yl = wid >> 1, xs = (wid & 1) * 16;
    const int pos0 = z0 * 1024 + (y0 + yl) * 32 + xs;
    const int rowIdx = z0 * 1156 + (y0 + yl) * 34 + xs;

    const char* baseA = (const char*)g_basis + (uint32_t)(rowIdx * 16) + lane * 4;
    const char* bfp   = (const char*)g_Bf + lane * 16;

    float d[8];
    #pragma unroll
    for (int i = 0; i < 8; i++) d[i] = 0.0f;

    if (kq == 0) {
        #pragma unroll
        for (int kc = 0; kc < 31; kc++) SPLINE_CHUNK(kc);
    } else if (kq == 1) {
        #pragma unroll
        for (int kc = 31; kc < 61; kc++) SPLINE_CHUNK(kc);
    } else if (kq == 2) {
        #pragma unroll
        for (int kc = 61; kc < 92; kc++) SPLINE_CHUNK(kc);
    } else {
        #pragma unroll
        for (int kc = 92; kc < 108; kc++) SPLINE_CHUNK(kc);
        const unsigned short* svRow = (const unsigned short*)g_silv + rowIdx;
        #pragma unroll
        for (int g = 0; g < 14; g++) {
            uint2 p01 = __ldg((const uint2*)&g_offT[16 * g + 2 * t4]);
            uint2 p23 = __ldg((const uint2*)&g_offT[16 * g + 8 + 2 * t4]);
            uint32_t u00 = __ldg(&svRow[g8 + p01.x]);
            uint32_t u01 = __ldg(&svRow[g8 + p01.y]);
            uint32_t u10 = __ldg(&svRow[g8 + 8 + p01.x]);
            uint32_t u11 = __ldg(&svRow[g8 + 8 + p01.y]);
            uint32_t u20 = __ldg(&svRow[g8 + p23.x]);
            uint32_t u21 = __ldg(&svRow[g8 + p23.y]);
            uint32_t u30 = __ldg(&svRow[g8 + 8 + p23.x]);
            uint32_t u31 = __ldg(&svRow[g8 + 8 + p23.y]);
            uint32_t a0 = u00 | (u01 << 16);
            uint32_t a1 = u10 | (u11 << 16);
            uint32_t a2 = u20 | (u21 << 16);
            uint32_t a3 = u30 | (u31 << 16);
            uint4 cb = __ldg((const uint4*)(bfp + (108 + g) * 512));
            MMA2(a0, a1, a2, a3, cb);
        }
    }

    // combine K quarters via atomics into zeroed output
    const int pr0 = pos0 + g8, pr1 = pr0 + 8;
    atomicAdd(&out[(2 * t4 + 0) * OSTRIDE + pr0], d[0]);
    atomicAdd(&out[(2 * t4 + 1) * OSTRIDE + pr0], d[1]);
    atomicAdd(&out[(2 * t4 + 0) * OSTRIDE + pr1], d[2]);
    atomicAdd(&out[(2 * t4 + 1) * OSTRIDE + pr1], d[3]);
    atomicAdd(&out[(2 * t4 + 8) * OSTRIDE + pr0], d[4]);
    atomicAdd(&out[(2 * t4 + 9) * OSTRIDE + pr0], d[5]);
    atomicAdd(&out[(2 * t4 + 8) * OSTRIDE + pr1], d[6]);
    atomicAdd(&out[(2 * t4 + 9) * OSTRIDE + pr1], d[7]);
}

extern "C" void kernel_launch(void* const* d_in, const int* in_sizes, int n_in,
                              void* d_out, int out_size) {
    const float* x  = (const float*)d_in[0];
    const float* bw = (const float*)d_in[1];
    const float* sw = (const float*)d_in[2];
    const float* sc = (const float*)d_in[3];

    cudaMemsetAsync(d_out, 0, (size_t)out_size * sizeof(float));
    prep_all<<<(PREP_TOTAL + 255) / 256, 256>>>(x, bw, sw, sc);

    kan_kernel<<<1024, 256>>>((float*)d_out);
}